// round 12
// baseline (speedup 1.0000x reference)
#include <cuda_runtime.h>
#include <cuda_fp16.h>
#include <cstdint>

#define KDIM 512
#define NDIM 256
#define BM 128
#define BN 128
#define KC 32
#define NSTAGE (KDIM / KC)   // 16

// smem: B only, double buffered: 2 x 8K
#define STAGE_SZ 8192
#define SMEM_TOTAL (2 * STAGE_SZ)

__device__ unsigned char g_mask[65536];
__device__ __half g_Wh[NDIM * KDIM];   // [n][k] = fp16(W[k][n])

// ---------------- helpers ----------------
__device__ __forceinline__ uint32_t smem_u32(const void* p) {
    uint32_t a;
    asm("{ .reg .u64 t; cvta.to.shared.u64 t, %1; cvt.u32.u64 %0, t; }" : "=r"(a) : "l"(p));
    return a;
}
// rows of 64B (4 x 16B chunks); chunk permuted by row -> conflict-free ldmatrix/cp.async
__device__ __forceinline__ uint32_t swz(uint32_t row, uint32_t chunk) {
    return row * 64u + ((chunk ^ ((row & 6u) >> 1)) << 4);
}
__device__ __forceinline__ void ldm4(uint32_t* r, uint32_t addr) {
    asm volatile("ldmatrix.sync.aligned.m8n8.x4.shared.b16 {%0,%1,%2,%3}, [%4];"
                 : "=r"(r[0]), "=r"(r[1]), "=r"(r[2]), "=r"(r[3]) : "r"(addr));
}
__device__ __forceinline__ void mma16816(float* d, const uint32_t* a, uint32_t b0, uint32_t b1) {
    asm volatile("mma.sync.aligned.m16n8k16.row.col.f32.f16.f16.f32 "
                 "{%0,%1,%2,%3}, {%4,%5,%6,%7}, {%8,%9}, {%0,%1,%2,%3};"
                 : "+f"(d[0]), "+f"(d[1]), "+f"(d[2]), "+f"(d[3])
                 : "r"(a[0]), "r"(a[1]), "r"(a[2]), "r"(a[3]), "r"(b0), "r"(b1));
}
__device__ __forceinline__ void cpa16(uint32_t dst, const void* src) {
    asm volatile("cp.async.cg.shared.global [%0], [%1], 16;" :: "r"(dst), "l"(src));
}
__device__ __forceinline__ uint32_t pack_h2f(float2 v) {
    __half2 t = __floats2half2_rn(v.x, v.y);
    return *(uint32_t*)&t;
}

// ---------------- prep kernels ----------------
__global__ void k_prep_w(const float* __restrict__ W) {
    int i = blockIdx.x * 256 + threadIdx.x;
    int k = i >> 8;
    int n = i & 255;
    g_Wh[(size_t)n * KDIM + k] = __float2half_rn(W[i]);   // W[k][n]
}
__global__ void k_zero_mask(int n4) {
    int i = blockIdx.x * blockDim.x + threadIdx.x;
    if (i < n4) ((uint4*)g_mask)[i] = make_uint4(0u, 0u, 0u, 0u);
}
__global__ void k_scatter_mask(const int* __restrict__ dst, int e4, int e) {
    int i = blockIdx.x * blockDim.x + threadIdx.x;
    if (i < e4) {
        int4 v = *(const int4*)(dst + 4 * i);
        g_mask[v.x] = 1; g_mask[v.y] = 1; g_mask[v.z] = 1; g_mask[v.w] = 1;
    }
    int r = e4 * 4 + i;
    if (r < e) g_mask[dst[r]] = 1;
}

// ---------------- GEMM: C = mask * (fp16(A) @ fp16(W)) ----------------
// A: direct global->register fragments (no smem round trip).
// B: cp.async double-buffered smem + ldmatrix (R7 discipline).
__global__ __launch_bounds__(256, 2)
void k_gemm(const float* __restrict__ A, float* __restrict__ C, int M)
{
    extern __shared__ char smem[];
    const uint32_t sbase = smem_u32(smem);
    const int tid  = threadIdx.x;
    const int lane = tid & 31;
    const int wid  = tid >> 5;
    const int warp_m = wid & 3;    // 0..3 -> 32 rows each
    const int warp_n = wid >> 2;   // 0..1 -> 64 cols each
    const int row0 = blockIdx.y * BM;
    const int n0   = blockIdx.x * BN;

    const int g  = lane >> 2;      // 0..7
    const int tg = lane & 3;       // 0..3

    // A fragment row pointers (clamped; invalid rows masked at store)
    const int rb = row0 + warp_m * 32;
    int r0 = rb + g;      if (r0 >= M) r0 = M - 1;
    int r1 = rb + g + 8;  if (r1 >= M) r1 = M - 1;
    int r2 = rb + g + 16; if (r2 >= M) r2 = M - 1;
    int r3 = rb + g + 24; if (r3 >= M) r3 = M - 1;
    const float* pr0 = A + (size_t)r0 * KDIM + tg * 2;
    const float* pr1 = A + (size_t)r1 * KDIM + tg * 2;
    const float* pr2 = A + (size_t)r2 * KDIM + tg * 2;
    const float* pr3 = A + (size_t)r3 * KDIM + tg * 2;

    // B loader: 128 rows x 32 f16 -> thread = (row tid>>1, half tid&1) 16 halves
    const int lrow  = tid >> 1;
    const int lhalf = tid & 1;
    const __half* bptr = g_Wh + (size_t)(n0 + lrow) * KDIM + lhalf * 16;
    const uint32_t b_sw0 = swz((uint32_t)lrow, (uint32_t)(lhalf * 2 + 0));
    const uint32_t b_sw1 = swz((uint32_t)lrow, (uint32_t)(lhalf * 2 + 1));

    auto issue_b = [&](int t) {
        const uint32_t buf = sbase + (uint32_t)(t & 1) * STAGE_SZ;
        const __half* s = bptr + t * KC;
        cpa16(buf + b_sw0, s);
        cpa16(buf + b_sw1, s + 8);
        asm volatile("cp.async.commit_group;" ::: "memory");
    };

    // Raw A loads for one k16 step (kn = global kstep 0..31)
    auto ldraw = [&](int kn, float2* v) {
        const int ko = kn * 16;
        v[0] = *(const float2*)(pr0 + ko);
        v[1] = *(const float2*)(pr1 + ko);
        v[2] = *(const float2*)(pr0 + ko + 8);
        v[3] = *(const float2*)(pr1 + ko + 8);
        v[4] = *(const float2*)(pr2 + ko);
        v[5] = *(const float2*)(pr3 + ko);
        v[6] = *(const float2*)(pr2 + ko + 8);
        v[7] = *(const float2*)(pr3 + ko + 8);
    };
    auto cvt8 = [&](const float2* v, uint32_t* ah) {
#pragma unroll
        for (int i = 0; i < 8; i++) ah[i] = pack_h2f(v[i]);
    };

    float acc[2][8][4];
#pragma unroll
    for (int i = 0; i < 2; i++)
#pragma unroll
        for (int j = 0; j < 8; j++)
#pragma unroll
            for (int q = 0; q < 4; q++) acc[i][j][q] = 0.f;

    const uint32_t bnrow = (uint32_t)(warp_n * 64 + (lane & 15));
    const uint32_t chalf = (uint32_t)(lane >> 4);

    auto mma_kstep = [&](uint32_t buf, uint32_t chunk, const uint32_t* ah) {
        uint32_t bh[4][4];
#pragma unroll
        for (int j = 0; j < 4; j++)
            ldm4(bh[j], buf + swz(bnrow + j * 16, chunk));
#pragma unroll
        for (int mb = 0; mb < 2; mb++)
#pragma unroll
            for (int j = 0; j < 4; j++) {
                mma16816(acc[mb][2 * j + 0], ah + mb * 4, bh[j][0], bh[j][2]);
                mma16816(acc[mb][2 * j + 1], ah + mb * 4, bh[j][1], bh[j][3]);
            }
    };

    // ---- prologue ----
    issue_b(0);
    uint32_t ahA[8], ahB[8];
    {
        float2 vt[8];
        ldraw(0, vt);
        cvt8(vt, ahA);
    }
    asm volatile("cp.async.wait_group 0;" ::: "memory");
    __syncthreads();

    for (int t = 0; t < NSTAGE; t++) {
        const uint32_t buf = sbase + (uint32_t)(t & 1) * STAGE_SZ;
        if (t + 1 < NSTAGE) issue_b(t + 1);

        float2 vt[8];
        // kstep 0 (even): compute with ahA, prefetch odd kstep -> ahB
        ldraw(2 * t + 1, vt);
        mma_kstep(buf, chalf, ahA);
        cvt8(vt, ahB);

        // kstep 1 (odd): compute with ahB, prefetch next even kstep -> ahA
        int kn2 = 2 * t + 2; if (kn2 >= 2 * NSTAGE) kn2 = 0;   // clamp (dead value)
        ldraw(kn2, vt);
        mma_kstep(buf, 2u + chalf, ahB);
        cvt8(vt, ahA);

        if (t + 1 < NSTAGE) {
            asm volatile("cp.async.wait_group 0;" ::: "memory");
            __syncthreads();
        }
    }

    // ---- epilogue: mask + store ----
#pragma unroll
    for (int mb = 0; mb < 2; mb++) {
        int r = row0 + warp_m * 32 + mb * 16 + g;
        float m0 = (r     < M) ? (float)g_mask[r]     : 0.f;
        float m1 = (r + 8 < M) ? (float)g_mask[r + 8] : 0.f;
#pragma unroll
        for (int nb = 0; nb < 8; nb++) {
            int c = n0 + warp_n * 64 + nb * 8 + tg * 2;
            if (r < M) {
                float2 o = make_float2(acc[mb][nb][0] * m0, acc[mb][nb][1] * m0);
                *(float2*)(C + (size_t)r * NDIM + c) = o;
            }
            if (r + 8 < M) {
                float2 o = make_float2(acc[mb][nb][2] * m1, acc[mb][nb][3] * m1);
                *(float2*)(C + (size_t)(r + 8) * NDIM + c) = o;
            }
        }
    }
}

// ---------------- launch: fork mask branch parallel to W-prep ----------------
extern "C" void kernel_launch(void* const* d_in, const int* in_sizes, int n_in,
                              void* d_out, int out_size) {
    const float* x  = (const float*)d_in[0];   // [N, 512]
    const int*   ei = (const int*)d_in[1];     // [2, E] int32
    const float* W  = (const float*)d_in[3];   // [512, 256]
    float* out = (float*)d_out;                // [N, 256]

    const int E = in_sizes[1] / 2;
    const int M = in_sizes[0] / KDIM;
    const int* dst = ei + E;
    const int e4 = E / 4;
    const int n4 = (M + 15) / 16;

    cudaFuncSetAttribute(k_gemm, cudaFuncAttributeMaxDynamicSharedMemorySize, SMEM_TOTAL);

    dim3 grid(NDIM / BN, (M + BM - 1) / BM);   // x = N-block (fastest varying)

    cudaStream_t s2 = nullptr;
    cudaEvent_t ev_fork = nullptr, ev_join = nullptr;
    bool forked =
        cudaStreamCreateWithFlags(&s2, cudaStreamNonBlocking) == cudaSuccess &&
        cudaEventCreateWithFlags(&ev_fork, cudaEventDisableTiming) == cudaSuccess &&
        cudaEventCreateWithFlags(&ev_join, cudaEventDisableTiming) == cudaSuccess;

    if (forked) {
        cudaEventRecord(ev_fork, 0);
        cudaStreamWaitEvent(s2, ev_fork, 0);
        k_zero_mask<<<(n4 + 255) / 256, 256, 0, s2>>>(n4);
        k_scatter_mask<<<(e4 + 255) / 256, 256, 0, s2>>>(dst, e4, E);
        cudaEventRecord(ev_join, s2);

        k_prep_w<<<(NDIM * KDIM) / 256, 256>>>(W);
        cudaStreamWaitEvent(0, ev_join, 0);
        k_gemm<<<grid, 256, SMEM_TOTAL>>>(x, out, M);
    } else {
        k_prep_w<<<(NDIM * KDIM) / 256, 256>>>(W);
        k_zero_mask<<<(n4 + 255) / 256, 256>>>(n4);
        k_scatter_mask<<<(e4 + 255) / 256, 256>>>(dst, e4, E);
        k_gemm<<<grid, 256, SMEM_TOTAL>>>(x, out, M);
    }

    if (ev_fork) cudaEventDestroy(ev_fork);
    if (ev_join) cudaEventDestroy(ev_join);
    if (s2) cudaStreamDestroy(s2);
}